// round 13
// baseline (speedup 1.0000x reference)
#include <cuda_runtime.h>
#include <cstdint>

#define N_NODES 100000
#define D 128
#define CSR_STRIDE 64      // fixed slots per node (actual deg <= 64)

// ---------------------------------------------------------------------------
// Scratch (__device__ globals: allocation-free rule)
// ---------------------------------------------------------------------------
__device__ __align__(128) float g_h[(size_t)N_NODES * D];            // 51.2 MB
__device__ __align__(128) int   g_cur[N_NODES];                      // fill counters -> degree
__device__ __align__(128) int   g_csr[(size_t)N_NODES * CSR_STRIDE]; // 25.6 MB
// Pre-permuted weights: [layer][kc 0..15][kk*128 + lane*4 + g] = W'[kc*16+kk][g*32+lane]
__device__ __align__(16) float g_wperm[2 * 16 * 2048];

#define FMA_F32X2(d, a, b) \
    asm("fma.rn.f32x2 %0, %1, %2, %0;" : "+l"(d) : "l"(a), "l"(b))
#define UNPACK_F32X2(lo, hi, in) \
    asm("mov.b64 {%0, %1}, %2;" : "=f"(lo), "=f"(hi) : "l"(in))

// ---------------------------------------------------------------------------
// Weight prep: permute both layers' [Wself;Wneigh] into GEMM SMEM layout
// ---------------------------------------------------------------------------
__global__ void prep_w_kernel(const float* __restrict__ Ws0, const float* __restrict__ Wn0,
                              const float* __restrict__ Ws1, const float* __restrict__ Wn1)
{
    int gid = blockIdx.x * blockDim.x + threadIdx.x;   // 65536
    if (gid >= 2 * 16 * 2048) return;
    int l  = gid >> 15;
    int r  = gid & 32767;
    int kc = r >> 11;
    int p  = r & 2047;
    int kk = p >> 7;
    int q  = p & 127;
    int lane = q >> 2;
    int g    = q & 3;
    int c = g * 32 + lane;
    int k = kc * 16 + kk;
    const float* Wsrc = (l == 0) ? ((k < 128) ? Ws0 : Wn0)
                                 : ((k < 128) ? Ws1 : Wn1);
    g_wperm[gid] = Wsrc[(size_t)(k & 127) * 128 + c];
}

// ---------------------------------------------------------------------------
// CSR fill (fixed stride). cur zeroed beforehand; becomes in-degree.
// ---------------------------------------------------------------------------
__global__ void fill_kernel(const int* __restrict__ src, const int* __restrict__ dst,
                            int* __restrict__ cur, int* __restrict__ csr, int n_edges)
{
    int i = blockIdx.x * blockDim.x + threadIdx.x;
    if (i < n_edges) {
        int d = dst[i];
        int pos = atomicAdd(cur + d, 1);
        if (pos < CSR_STRIDE)
            csr[(size_t)d * CSR_STRIDE + pos] = src[i];
    }
}

// ---------------------------------------------------------------------------
// FUSED layer kernel, 128-ROW TILE:
//   Phase 1: fp32 gather of neighbor means (warp handles 16 rows as pairs).
//   Phase 2: K=256 f32x2 GEMM; thread = 16 rows x 4 cols. W chunk read once
//            per warp serves 2x the rows (halved duplication vs 64-row tile).
// 256 threads, occ 2 (smem 94KB).
// ---------------------------------------------------------------------------
#define ROWS 128
#define AS_STRIDE 36
#define MS_STRIDE 132
#define DYN_FLOATS (ROWS * MS_STRIDE + ROWS * AS_STRIDE + 2048)
#define DYN_BYTES  (DYN_FLOATS * 4)    // 94208

// gather one 4-edge batch for row pointer p into acc (int4 index load)
#define GATHER4(p, i, acc) do {                                                  \
    int4 s4 = *reinterpret_cast<const int4*>((p) + (i));                         \
    float4 v0 = *reinterpret_cast<const float4*>(A + (size_t)s4.x * D + lane4);  \
    float4 v1 = *reinterpret_cast<const float4*>(A + (size_t)s4.y * D + lane4);  \
    float4 v2 = *reinterpret_cast<const float4*>(A + (size_t)s4.z * D + lane4);  \
    float4 v3 = *reinterpret_cast<const float4*>(A + (size_t)s4.w * D + lane4);  \
    (acc).x += (v0.x + v1.x) + (v2.x + v3.x);                                    \
    (acc).y += (v0.y + v1.y) + (v2.y + v3.y);                                    \
    (acc).z += (v0.z + v1.z) + (v2.z + v3.z);                                    \
    (acc).w += (v0.w + v1.w) + (v2.w + v3.w);                                    \
} while (0)

template <bool FUSE_LN>
__global__ void __launch_bounds__(256) sage_fused_kernel(
    const float* __restrict__ A,       // [N,128] layer input
    const int*   __restrict__ csr,
    const int*   __restrict__ deg,
    const int*   __restrict__ in_deg,
    const float* __restrict__ Wp_g,    // pre-permuted weights [16*2048]
    const float* __restrict__ bias,
    const float* __restrict__ ln_g,
    const float* __restrict__ ln_b,
    float*       __restrict__ Out)     // [N,128]
{
    extern __shared__ __align__(16) float dynf[];
    float* smsg = dynf;                        // 128*132
    float* As2  = dynf + ROWS * MS_STRIDE;     // 128*36
    float* Wp   = As2 + ROWS * AS_STRIDE;      // 2048

    const int t    = threadIdx.x;
    const int tx   = t & 31;
    const int ty   = t >> 5;
    const int row0 = blockIdx.x * ROWS;

    // ================= Phase 1: interleaved-pair gather (16 rows/warp) ======
    {
        const int lane4 = tx * 4;
#pragma unroll 1
        for (int jp = 0; jp < 16; jp += 2) {
            const int lr0 = ty * 16 + jp;
            const int lr1 = lr0 + 1;
            const int gr0 = row0 + lr0;
            const int gr1 = row0 + lr1;
            const bool ok0 = gr0 < N_NODES;
            const bool ok1 = gr1 < N_NODES;
            int cnt0 = ok0 ? __ldg(deg + gr0) : 0;
            int cnt1 = ok1 ? __ldg(deg + gr1) : 0;
            if (cnt0 > CSR_STRIDE) cnt0 = CSR_STRIDE;
            if (cnt1 > CSR_STRIDE) cnt1 = CSR_STRIDE;
            const int* p0 = csr + (size_t)gr0 * CSR_STRIDE;
            const int* p1 = csr + (size_t)gr1 * CSR_STRIDE;

            float4 acc0 = make_float4(0.f, 0.f, 0.f, 0.f);
            float4 acc1 = make_float4(0.f, 0.f, 0.f, 0.f);

            const int nb0 = cnt0 >> 2;
            const int nb1 = cnt1 >> 2;
            const int nbm = max(nb0, nb1);
#pragma unroll 1
            for (int b = 0; b < nbm; ++b) {
                if (b < nb0) GATHER4(p0, b * 4, acc0);
                if (b < nb1) GATHER4(p1, b * 4, acc1);
            }
            for (int i = nb0 * 4; i < cnt0; ++i) {
                int s = __ldg(p0 + i);
                float4 v = *reinterpret_cast<const float4*>(A + (size_t)s * D + lane4);
                acc0.x += v.x; acc0.y += v.y; acc0.z += v.z; acc0.w += v.w;
            }
            for (int i = nb1 * 4; i < cnt1; ++i) {
                int s = __ldg(p1 + i);
                float4 v = *reinterpret_cast<const float4*>(A + (size_t)s * D + lane4);
                acc1.x += v.x; acc1.y += v.y; acc1.z += v.z; acc1.w += v.w;
            }

            if (ok0) {
                float inv = 1.0f / (float)max(__ldg(in_deg + gr0), 1);
                acc0.x *= inv; acc0.y *= inv; acc0.z *= inv; acc0.w *= inv;
            }
            if (ok1) {
                float inv = 1.0f / (float)max(__ldg(in_deg + gr1), 1);
                acc1.x *= inv; acc1.y *= inv; acc1.z *= inv; acc1.w *= inv;
            }
            *reinterpret_cast<float4*>(smsg + lr0 * MS_STRIDE + lane4) = acc0;
            *reinterpret_cast<float4*>(smsg + lr1 * MS_STRIDE + lane4) = acc1;
        }
    }
    __syncthreads();

    // ================= Phase 2: K=256 f32x2 GEMM, 16 rows/thread ===========
    const int lr  = t >> 2;          // rows lr and lr+64 staged by this thread
    const int lk4 = (t & 3) << 2;
    const int gr_a = row0 + lr;
    const int gr_b = row0 + lr + 64;
    const bool ok_a = gr_a < N_NODES;
    const bool ok_b = gr_b < N_NODES;

    unsigned long long acc[16][2];
#pragma unroll
    for (int j = 0; j < 16; ++j) { acc[j][0] = 0ull; acc[j][1] = 0ull; }

    // initial loads (chunk 0)
    float4 aA = ok_a ? *reinterpret_cast<const float4*>(A + (size_t)gr_a * 128 + lk4)
                     : make_float4(0.f, 0.f, 0.f, 0.f);
    float4 aB = ok_b ? *reinterpret_cast<const float4*>(A + (size_t)gr_b * 128 + lk4)
                     : make_float4(0.f, 0.f, 0.f, 0.f);
    float4 w0 = *reinterpret_cast<const float4*>(Wp_g + t * 4);
    float4 w1 = *reinterpret_cast<const float4*>(Wp_g + (t + 256) * 4);

#pragma unroll 1
    for (int kc = 0; kc < 16; ++kc) {
        __syncthreads();   // previous chunk's compute done
        *reinterpret_cast<float4*>(As2 + lr * AS_STRIDE + lk4 * 2) =
            make_float4(aA.x, aA.x, aA.y, aA.y);
        *reinterpret_cast<float4*>(As2 + lr * AS_STRIDE + lk4 * 2 + 4) =
            make_float4(aA.z, aA.z, aA.w, aA.w);
        *reinterpret_cast<float4*>(As2 + (lr + 64) * AS_STRIDE + lk4 * 2) =
            make_float4(aB.x, aB.x, aB.y, aB.y);
        *reinterpret_cast<float4*>(As2 + (lr + 64) * AS_STRIDE + lk4 * 2 + 4) =
            make_float4(aB.z, aB.z, aB.w, aB.w);
        *reinterpret_cast<float4*>(Wp + t * 4)         = w0;
        *reinterpret_cast<float4*>(Wp + (t + 256) * 4) = w1;

        // issue next chunk's loads; they land during compute
        if (kc < 15) {
            const int kn = kc + 1;
            if (kn < 8) {
                aA = ok_a ? *reinterpret_cast<const float4*>(
                                A + (size_t)gr_a * 128 + kn * 16 + lk4)
                          : make_float4(0.f, 0.f, 0.f, 0.f);
                aB = ok_b ? *reinterpret_cast<const float4*>(
                                A + (size_t)gr_b * 128 + kn * 16 + lk4)
                          : make_float4(0.f, 0.f, 0.f, 0.f);
            } else {
                aA = *reinterpret_cast<const float4*>(
                    smsg + lr * MS_STRIDE + (kn - 8) * 16 + lk4);
                aB = *reinterpret_cast<const float4*>(
                    smsg + (lr + 64) * MS_STRIDE + (kn - 8) * 16 + lk4);
            }
            w0 = *reinterpret_cast<const float4*>(Wp_g + kn * 2048 + t * 4);
            w1 = *reinterpret_cast<const float4*>(Wp_g + kn * 2048 + (t + 256) * 4);
        }
        __syncthreads();   // As2/Wp visible

#pragma unroll
        for (int m = 0; m < 8; ++m) {
            ulonglong2 wA = *reinterpret_cast<const ulonglong2*>(Wp + (2 * m) * 128 + tx * 4);
            ulonglong2 wB = *reinterpret_cast<const ulonglong2*>(Wp + (2 * m + 1) * 128 + tx * 4);
#pragma unroll
            for (int j = 0; j < 16; ++j) {
                ulonglong2 ap = *reinterpret_cast<const ulonglong2*>(
                    As2 + (ty + j * 8) * AS_STRIDE + m * 4);
                FMA_F32X2(acc[j][0], ap.x, wA.x);   // cols (tx, tx+32)
                FMA_F32X2(acc[j][1], ap.x, wA.y);   // cols (tx+64, tx+96)
                FMA_F32X2(acc[j][0], ap.y, wB.x);
                FMA_F32X2(acc[j][1], ap.y, wB.y);
            }
        }
    }

    // ================= Epilogue =================
    float bia[4], lg[4], lb[4];
#pragma unroll
    for (int c = 0; c < 4; ++c) {
        int col = tx + 32 * c;
        bia[c] = __ldg(bias + col);
        if (FUSE_LN) { lg[c] = __ldg(ln_g + col); lb[c] = __ldg(ln_b + col); }
    }

#pragma unroll
    for (int j = 0; j < 16; ++j) {
        int grow = row0 + ty + j * 8;
        float v[4];
        UNPACK_F32X2(v[0], v[1], acc[j][0]);
        UNPACK_F32X2(v[2], v[3], acc[j][1]);
#pragma unroll
        for (int c = 0; c < 4; ++c) v[c] += bia[c];

        if (FUSE_LN) {
            float s = v[0] + v[1] + v[2] + v[3];
#pragma unroll
            for (int o = 16; o > 0; o >>= 1) s += __shfl_xor_sync(0xffffffffu, s, o);
            float mu = s * (1.0f / 128.0f);
            float d2 = 0.f;
#pragma unroll
            for (int c = 0; c < 4; ++c) { float dd = v[c] - mu; d2 += dd * dd; }
#pragma unroll
            for (int o = 16; o > 0; o >>= 1) d2 += __shfl_xor_sync(0xffffffffu, d2, o);
            float rstd = rsqrtf(d2 * (1.0f / 128.0f) + 1e-5f);
#pragma unroll
            for (int c = 0; c < 4; ++c) {
                float y = (v[c] - mu) * rstd * lg[c] + lb[c];
                v[c] = fmaxf(y, 0.0f);
            }
        }

        if (grow < N_NODES) {
#pragma unroll
            for (int c = 0; c < 4; ++c)
                Out[(size_t)grow * 128 + tx + 32 * c] = v[c];
        }
    }
}

// ---------------------------------------------------------------------------
// Launch.  Inputs: feat, W_self0, W_neigh0, b0, W_self1, W_neigh1, b1,
//                  ln_g, ln_b, edge_src, edge_dst, in_deg
// Launch order: [memset, prep, fill, fused0, fused1] -> ncu 5th = fused1.
// ---------------------------------------------------------------------------
extern "C" void kernel_launch(void* const* d_in, const int* in_sizes, int n_in,
                              void* d_out, int out_size)
{
    const float* feat = (const float*)d_in[0];
    const float* Ws0  = (const float*)d_in[1];
    const float* Wn0  = (const float*)d_in[2];
    const float* b0   = (const float*)d_in[3];
    const float* Ws1  = (const float*)d_in[4];
    const float* Wn1  = (const float*)d_in[5];
    const float* b1   = (const float*)d_in[6];
    const float* lng  = (const float*)d_in[7];
    const float* lnb  = (const float*)d_in[8];
    const int*   esrc = (const int*)d_in[9];
    const int*   edst = (const int*)d_in[10];
    const int*   indeg= (const int*)d_in[11];
    const int n_edges = in_sizes[9];

    float *h = nullptr, *wperm = nullptr;
    int *cur = nullptr, *csr = nullptr;
    cudaGetSymbolAddress((void**)&h,     g_h);
    cudaGetSymbolAddress((void**)&cur,   g_cur);
    cudaGetSymbolAddress((void**)&csr,   g_csr);
    cudaGetSymbolAddress((void**)&wperm, g_wperm);

    const int eb          = (n_edges + 255) / 256;
    const int gemm_blocks = (N_NODES + ROWS - 1) / ROWS;   // 782

    cudaFuncSetAttribute(sage_fused_kernel<true>,
                         cudaFuncAttributeMaxDynamicSharedMemorySize, DYN_BYTES);
    cudaFuncSetAttribute(sage_fused_kernel<false>,
                         cudaFuncAttributeMaxDynamicSharedMemorySize, DYN_BYTES);

    // (1) zero fill counters
    cudaMemsetAsync(cur, 0, N_NODES * sizeof(int), 0);
    // (2) weight permutation
    prep_w_kernel<<<(2 * 16 * 2048 + 255) / 256, 256>>>(Ws0, Wn0, Ws1, Wn1);
    // (3) fixed-stride CSR fill (cur becomes degree)
    fill_kernel<<<eb, 256>>>(esrc, edst, cur, csr, n_edges);

    // (4) Layer 0 (gather + GEMM + LN + ReLU fused)
    sage_fused_kernel<true><<<gemm_blocks, 256, DYN_BYTES>>>(
        feat, csr, cur, indeg, wperm, b0, lng, lnb, h);

    // (5) Layer 1  <- profiled launch
    sage_fused_kernel<false><<<gemm_blocks, 256, DYN_BYTES>>>(
        h, csr, cur, indeg, wperm + 16 * 2048, b1, lng, lnb, (float*)d_out);
}

// round 14
// speedup vs baseline: 1.5980x; 1.5980x over previous
#include <cuda_runtime.h>
#include <cstdint>

#define N_NODES 100000
#define D 128
#define CSR_STRIDE 64      // fixed slots per node (actual deg <= 64)

// ---------------------------------------------------------------------------
// Scratch (__device__ globals: allocation-free rule)
// ---------------------------------------------------------------------------
__device__ __align__(128) float g_h[(size_t)N_NODES * D];            // 51.2 MB
__device__ __align__(128) int   g_cur[N_NODES];                      // fill counters -> degree
__device__ __align__(128) int   g_csr[(size_t)N_NODES * CSR_STRIDE]; // 25.6 MB
// Pre-permuted weights: [layer][kc 0..15][kk*128 + lane*4 + g] = W'[kc*16+kk][g*32+lane]
__device__ __align__(16) float g_wperm[2 * 16 * 2048];

#define FMA_F32X2(d, a, b) \
    asm("fma.rn.f32x2 %0, %1, %2, %0;" : "+l"(d) : "l"(a), "l"(b))
#define UNPACK_F32X2(lo, hi, in) \
    asm("mov.b64 {%0, %1}, %2;" : "=f"(lo), "=f"(hi) : "l"(in))
// duplicate one fp32 into a packed (a,a) 64-bit operand
#define DUP_F32X2(d, a) \
    asm("mov.b64 %0, {%1, %1};" : "=l"(d) : "f"(a))

// ---------------------------------------------------------------------------
// Weight prep: permute both layers' [Wself;Wneigh] into GEMM SMEM layout
// ---------------------------------------------------------------------------
__global__ void prep_w_kernel(const float* __restrict__ Ws0, const float* __restrict__ Wn0,
                              const float* __restrict__ Ws1, const float* __restrict__ Wn1)
{
    int gid = blockIdx.x * blockDim.x + threadIdx.x;   // 65536
    if (gid >= 2 * 16 * 2048) return;
    int l  = gid >> 15;
    int r  = gid & 32767;
    int kc = r >> 11;
    int p  = r & 2047;
    int kk = p >> 7;
    int q  = p & 127;
    int lane = q >> 2;
    int g    = q & 3;
    int c = g * 32 + lane;
    int k = kc * 16 + kk;
    const float* Wsrc = (l == 0) ? ((k < 128) ? Ws0 : Wn0)
                                 : ((k < 128) ? Ws1 : Wn1);
    g_wperm[gid] = Wsrc[(size_t)(k & 127) * 128 + c];
}

// ---------------------------------------------------------------------------
// CSR fill (fixed stride). cur zeroed beforehand; becomes in-degree.
// ---------------------------------------------------------------------------
__global__ void fill_kernel(const int* __restrict__ src, const int* __restrict__ dst,
                            int* __restrict__ cur, int* __restrict__ csr, int n_edges)
{
    int i = blockIdx.x * blockDim.x + threadIdx.x;
    if (i < n_edges) {
        int d = dst[i];
        int pos = atomicAdd(cur + d, 1);
        if (pos < CSR_STRIDE)
            csr[(size_t)d * CSR_STRIDE + pos] = src[i];
    }
}

// ---------------------------------------------------------------------------
// FUSED layer kernel (R12 base; GEMM A-path: scalar SMEM + register dup):
//   Phase 1: fp32 gather of neighbor means (interleaved row pairs, int4 idx).
//   Phase 2: K=256 f32x2 GEMM. A staged as plain scalars (1 STS.128/thread,
//            LDS.128 = 4 k's); (a,a) packs built in-register. 25% fewer L1
//            wavefronts in the inner loop.
// Tile 64 rows x 128 cols, 256 threads.
// ---------------------------------------------------------------------------
#define AS_STRIDE 20       // 16 scalars + pad (20 mod 32 = 4 -> conflict-free)
#define MS_STRIDE 132
#define DYN_FLOATS (64 * MS_STRIDE + 64 * AS_STRIDE + 2048)
#define DYN_BYTES  (DYN_FLOATS * 4)    // 47104

// gather one 4-edge batch for row pointer p into acc (int4 index load)
#define GATHER4(p, i, acc) do {                                                  \
    int4 s4 = *reinterpret_cast<const int4*>((p) + (i));                         \
    float4 v0 = *reinterpret_cast<const float4*>(A + (size_t)s4.x * D + lane4);  \
    float4 v1 = *reinterpret_cast<const float4*>(A + (size_t)s4.y * D + lane4);  \
    float4 v2 = *reinterpret_cast<const float4*>(A + (size_t)s4.z * D + lane4);  \
    float4 v3 = *reinterpret_cast<const float4*>(A + (size_t)s4.w * D + lane4);  \
    (acc).x += (v0.x + v1.x) + (v2.x + v3.x);                                    \
    (acc).y += (v0.y + v1.y) + (v2.y + v3.y);                                    \
    (acc).z += (v0.z + v1.z) + (v2.z + v3.z);                                    \
    (acc).w += (v0.w + v1.w) + (v2.w + v3.w);                                    \
} while (0)

template <bool FUSE_LN>
__global__ void __launch_bounds__(256) sage_fused_kernel(
    const float* __restrict__ A,       // [N,128] layer input
    const int*   __restrict__ csr,
    const int*   __restrict__ deg,
    const int*   __restrict__ in_deg,
    const float* __restrict__ Wp_g,    // pre-permuted weights [16*2048]
    const float* __restrict__ bias,
    const float* __restrict__ ln_g,
    const float* __restrict__ ln_b,
    float*       __restrict__ Out)     // [N,128]
{
    extern __shared__ __align__(16) float dynf[];
    float* smsg = dynf;                       // 64*132
    float* As2  = dynf + 64 * MS_STRIDE;      // 64*20 (scalar A chunk)
    float* Wp   = As2 + 64 * AS_STRIDE;       // 2048

    const int t    = threadIdx.x;
    const int tx   = t & 31;
    const int ty   = t >> 5;
    const int row0 = blockIdx.x * 64;

    // ================= Phase 1: interleaved-pair gather =================
    {
        const int lane4 = tx * 4;
#pragma unroll 1
        for (int jp = 0; jp < 8; jp += 2) {
            const int lr0 = ty * 8 + jp;
            const int lr1 = lr0 + 1;
            const int gr0 = row0 + lr0;
            const int gr1 = row0 + lr1;
            const bool ok0 = gr0 < N_NODES;
            const bool ok1 = gr1 < N_NODES;
            int cnt0 = ok0 ? __ldg(deg + gr0) : 0;
            int cnt1 = ok1 ? __ldg(deg + gr1) : 0;
            if (cnt0 > CSR_STRIDE) cnt0 = CSR_STRIDE;
            if (cnt1 > CSR_STRIDE) cnt1 = CSR_STRIDE;
            const int* p0 = csr + (size_t)gr0 * CSR_STRIDE;
            const int* p1 = csr + (size_t)gr1 * CSR_STRIDE;

            float4 acc0 = make_float4(0.f, 0.f, 0.f, 0.f);
            float4 acc1 = make_float4(0.f, 0.f, 0.f, 0.f);

            const int nb0 = cnt0 >> 2;
            const int nb1 = cnt1 >> 2;
            const int nbm = max(nb0, nb1);
#pragma unroll 1
            for (int b = 0; b < nbm; ++b) {
                if (b < nb0) GATHER4(p0, b * 4, acc0);
                if (b < nb1) GATHER4(p1, b * 4, acc1);
            }
            for (int i = nb0 * 4; i < cnt0; ++i) {
                int s = __ldg(p0 + i);
                float4 v = *reinterpret_cast<const float4*>(A + (size_t)s * D + lane4);
                acc0.x += v.x; acc0.y += v.y; acc0.z += v.z; acc0.w += v.w;
            }
            for (int i = nb1 * 4; i < cnt1; ++i) {
                int s = __ldg(p1 + i);
                float4 v = *reinterpret_cast<const float4*>(A + (size_t)s * D + lane4);
                acc1.x += v.x; acc1.y += v.y; acc1.z += v.z; acc1.w += v.w;
            }

            if (ok0) {
                float inv = 1.0f / (float)max(__ldg(in_deg + gr0), 1);
                acc0.x *= inv; acc0.y *= inv; acc0.z *= inv; acc0.w *= inv;
            }
            if (ok1) {
                float inv = 1.0f / (float)max(__ldg(in_deg + gr1), 1);
                acc1.x *= inv; acc1.y *= inv; acc1.z *= inv; acc1.w *= inv;
            }
            *reinterpret_cast<float4*>(smsg + lr0 * MS_STRIDE + lane4) = acc0;
            *reinterpret_cast<float4*>(smsg + lr1 * MS_STRIDE + lane4) = acc1;
        }
    }
    __syncthreads();

    // ================= Phase 2: K=256 f32x2 GEMM =================
    const int lr  = t >> 2;
    const int lk4 = (t & 3) << 2;
    const int grow_l = row0 + lr;
    const bool okl = grow_l < N_NODES;

    unsigned long long acc[8][2];
#pragma unroll
    for (int j = 0; j < 8; ++j) { acc[j][0] = 0ull; acc[j][1] = 0ull; }

    // initial loads (chunk 0)
    float4 a4 = okl ? *reinterpret_cast<const float4*>(A + (size_t)grow_l * 128 + lk4)
                    : make_float4(0.f, 0.f, 0.f, 0.f);
    float4 w0 = *reinterpret_cast<const float4*>(Wp_g + t * 4);
    float4 w1 = *reinterpret_cast<const float4*>(Wp_g + (t + 256) * 4);

#pragma unroll 1
    for (int kc = 0; kc < 16; ++kc) {
        __syncthreads();   // previous chunk's compute done -> As2/Wp free
        *reinterpret_cast<float4*>(As2 + lr * AS_STRIDE + lk4) = a4;   // scalar A
        *reinterpret_cast<float4*>(Wp + t * 4)         = w0;
        *reinterpret_cast<float4*>(Wp + (t + 256) * 4) = w1;

        // issue next chunk's loads NOW; they land during the compute below
        if (kc < 15) {
            const int kn = kc + 1;
            if (kn < 8) {
                a4 = okl ? *reinterpret_cast<const float4*>(
                               A + (size_t)grow_l * 128 + kn * 16 + lk4)
                         : make_float4(0.f, 0.f, 0.f, 0.f);
            } else {
                a4 = *reinterpret_cast<const float4*>(
                    smsg + lr * MS_STRIDE + (kn - 8) * 16 + lk4);
            }
            w0 = *reinterpret_cast<const float4*>(Wp_g + kn * 2048 + t * 4);
            w1 = *reinterpret_cast<const float4*>(Wp_g + kn * 2048 + (t + 256) * 4);
        }
        __syncthreads();   // As2/Wp visible

        // 4 k's per m2 step: 4 W-LDS.128 + per-row 1 A-LDS.128 + reg dups
#pragma unroll
        for (int m2 = 0; m2 < 4; ++m2) {
            ulonglong2 wv0 = *reinterpret_cast<const ulonglong2*>(Wp + (4 * m2 + 0) * 128 + tx * 4);
            ulonglong2 wv1 = *reinterpret_cast<const ulonglong2*>(Wp + (4 * m2 + 1) * 128 + tx * 4);
            ulonglong2 wv2 = *reinterpret_cast<const ulonglong2*>(Wp + (4 * m2 + 2) * 128 + tx * 4);
            ulonglong2 wv3 = *reinterpret_cast<const ulonglong2*>(Wp + (4 * m2 + 3) * 128 + tx * 4);
#pragma unroll
            for (int j = 0; j < 8; ++j) {
                float4 av = *reinterpret_cast<const float4*>(
                    As2 + (ty + j * 8) * AS_STRIDE + m2 * 4);   // broadcast, 4 k's
                unsigned long long d0, d1, d2, d3;
                DUP_F32X2(d0, av.x);
                DUP_F32X2(d1, av.y);
                DUP_F32X2(d2, av.z);
                DUP_F32X2(d3, av.w);
                FMA_F32X2(acc[j][0], d0, wv0.x);
                FMA_F32X2(acc[j][1], d0, wv0.y);
                FMA_F32X2(acc[j][0], d1, wv1.x);
                FMA_F32X2(acc[j][1], d1, wv1.y);
                FMA_F32X2(acc[j][0], d2, wv2.x);
                FMA_F32X2(acc[j][1], d2, wv2.y);
                FMA_F32X2(acc[j][0], d3, wv3.x);
                FMA_F32X2(acc[j][1], d3, wv3.y);
            }
        }
    }

    // ================= Epilogue =================
    float bia[4], lg[4], lb[4];
#pragma unroll
    for (int c = 0; c < 4; ++c) {
        int col = tx + 32 * c;
        bia[c] = __ldg(bias + col);
        if (FUSE_LN) { lg[c] = __ldg(ln_g + col); lb[c] = __ldg(ln_b + col); }
    }

#pragma unroll
    for (int j = 0; j < 8; ++j) {
        int grow = row0 + ty + j * 8;
        float v[4];
        UNPACK_F32X2(v[0], v[1], acc[j][0]);
        UNPACK_F32X2(v[2], v[3], acc[j][1]);
#pragma unroll
        for (int c = 0; c < 4; ++c) v[c] += bia[c];

        if (FUSE_LN) {
            float s = v[0] + v[1] + v[2] + v[3];
#pragma unroll
            for (int o = 16; o > 0; o >>= 1) s += __shfl_xor_sync(0xffffffffu, s, o);
            float mu = s * (1.0f / 128.0f);
            float d2 = 0.f;
#pragma unroll
            for (int c = 0; c < 4; ++c) { float dd = v[c] - mu; d2 += dd * dd; }
#pragma unroll
            for (int o = 16; o > 0; o >>= 1) d2 += __shfl_xor_sync(0xffffffffu, d2, o);
            float rstd = rsqrtf(d2 * (1.0f / 128.0f) + 1e-5f);
#pragma unroll
            for (int c = 0; c < 4; ++c) {
                float y = (v[c] - mu) * rstd * lg[c] + lb[c];
                v[c] = fmaxf(y, 0.0f);
            }
        }

        if (grow < N_NODES) {
#pragma unroll
            for (int c = 0; c < 4; ++c)
                Out[(size_t)grow * 128 + tx + 32 * c] = v[c];
        }
    }
}

// ---------------------------------------------------------------------------
// Launch.  Inputs: feat, W_self0, W_neigh0, b0, W_self1, W_neigh1, b1,
//                  ln_g, ln_b, edge_src, edge_dst, in_deg
// Launch order: [memset, prep, fill, fused0, fused1] -> ncu 5th = fused1.
// ---------------------------------------------------------------------------
extern "C" void kernel_launch(void* const* d_in, const int* in_sizes, int n_in,
                              void* d_out, int out_size)
{
    const float* feat = (const float*)d_in[0];
    const float* Ws0  = (const float*)d_in[1];
    const float* Wn0  = (const float*)d_in[2];
    const float* b0   = (const float*)d_in[3];
    const float* Ws1  = (const float*)d_in[4];
    const float* Wn1  = (const float*)d_in[5];
    const float* b1   = (const float*)d_in[6];
    const float* lng  = (const float*)d_in[7];
    const float* lnb  = (const float*)d_in[8];
    const int*   esrc = (const int*)d_in[9];
    const int*   edst = (const int*)d_in[10];
    const int*   indeg= (const int*)d_in[11];
    const int n_edges = in_sizes[9];

    float *h = nullptr, *wperm = nullptr;
    int *cur = nullptr, *csr = nullptr;
    cudaGetSymbolAddress((void**)&h,     g_h);
    cudaGetSymbolAddress((void**)&cur,   g_cur);
    cudaGetSymbolAddress((void**)&csr,   g_csr);
    cudaGetSymbolAddress((void**)&wperm, g_wperm);

    const int eb          = (n_edges + 255) / 256;
    const int gemm_blocks = (N_NODES + 63) / 64;   // 1563

    cudaFuncSetAttribute(sage_fused_kernel<true>,
                         cudaFuncAttributeMaxDynamicSharedMemorySize, DYN_BYTES);
    cudaFuncSetAttribute(sage_fused_kernel<false>,
                         cudaFuncAttributeMaxDynamicSharedMemorySize, DYN_BYTES);

    // (1) zero fill counters
    cudaMemsetAsync(cur, 0, N_NODES * sizeof(int), 0);
    // (2) weight permutation
    prep_w_kernel<<<(2 * 16 * 2048 + 255) / 256, 256>>>(Ws0, Wn0, Ws1, Wn1);
    // (3) fixed-stride CSR fill (cur becomes degree)
    fill_kernel<<<eb, 256>>>(esrc, edst, cur, csr, n_edges);

    // (4) Layer 0 (gather + GEMM + LN + ReLU fused)
    sage_fused_kernel<true><<<gemm_blocks, 256, DYN_BYTES>>>(
        feat, csr, cur, indeg, wperm, b0, lng, lnb, h);

    // (5) Layer 1  <- profiled launch
    sage_fused_kernel<false><<<gemm_blocks, 256, DYN_BYTES>>>(
        h, csr, cur, indeg, wperm + 16 * 2048, b1, lng, lnb, (float*)d_out);
}

// round 16
// speedup vs baseline: 1.8217x; 1.1400x over previous
#include <cuda_runtime.h>
#include <cstdint>

#define N_NODES 100000
#define D 128
#define CSR_STRIDE 64      // fixed slots per node (actual deg <= 64)

// ---------------------------------------------------------------------------
// Scratch (__device__ globals: allocation-free rule)
// ---------------------------------------------------------------------------
__device__ __align__(128) float g_h[(size_t)N_NODES * D];            // 51.2 MB
__device__ __align__(128) float g_msg[(size_t)N_NODES * D];          // 51.2 MB
__device__ __align__(128) int   g_cur[N_NODES];                      // fill counters -> degree
__device__ __align__(128) int   g_csr[(size_t)N_NODES * CSR_STRIDE]; // 25.6 MB
// Pre-permuted weights: [layer][kc 0..15][kk*128 + lane*4 + g] = W'[kc*16+kk][g*32+lane]
__device__ __align__(16) float g_wperm[2 * 16 * 2048];

#define FMA_F32X2(d, a, b) \
    asm("fma.rn.f32x2 %0, %1, %2, %0;" : "+l"(d) : "l"(a), "l"(b))
#define UNPACK_F32X2(lo, hi, in) \
    asm("mov.b64 {%0, %1}, %2;" : "=f"(lo), "=f"(hi) : "l"(in))

// ---------------------------------------------------------------------------
// Weight prep: permute both layers' [Wself;Wneigh] into GEMM SMEM layout
// ---------------------------------------------------------------------------
__global__ void prep_w_kernel(const float* __restrict__ Ws0, const float* __restrict__ Wn0,
                              const float* __restrict__ Ws1, const float* __restrict__ Wn1)
{
    int gid = blockIdx.x * blockDim.x + threadIdx.x;   // 65536
    if (gid >= 2 * 16 * 2048) return;
    int l  = gid >> 15;
    int r  = gid & 32767;
    int kc = r >> 11;
    int p  = r & 2047;
    int kk = p >> 7;
    int q  = p & 127;
    int lane = q >> 2;
    int g    = q & 3;
    int c = g * 32 + lane;
    int k = kc * 16 + kk;
    const float* Wsrc = (l == 0) ? ((k < 128) ? Ws0 : Wn0)
                                 : ((k < 128) ? Ws1 : Wn1);
    g_wperm[gid] = Wsrc[(size_t)(k & 127) * 128 + c];
}

// ---------------------------------------------------------------------------
// CSR fill (fixed stride). cur zeroed beforehand; becomes in-degree.
// ---------------------------------------------------------------------------
__global__ void fill_kernel(const int* __restrict__ src, const int* __restrict__ dst,
                            int* __restrict__ cur, int* __restrict__ csr, int n_edges)
{
    int i = blockIdx.x * blockDim.x + threadIdx.x;
    if (i < n_edges) {
        int d = dst[i];
        int pos = atomicAdd(cur + d, 1);
        if (pos < CSR_STRIDE)
            csr[(size_t)d * CSR_STRIDE + pos] = src[i];
    }
}

// ---------------------------------------------------------------------------
// STANDALONE aggregate: warp handles an interleaved PAIR of nodes (2 load
// chains, MLP 8). 16 nodes per 256-thread CTA, no barriers, pure gather.
// msg[n] = mean of incoming neighbor rows of A.
// ---------------------------------------------------------------------------
#define GATHER4(p, i, acc) do {                                                  \
    int4 s4 = *reinterpret_cast<const int4*>((p) + (i));                         \
    float4 v0 = *reinterpret_cast<const float4*>(A + (size_t)s4.x * D + lane4);  \
    float4 v1 = *reinterpret_cast<const float4*>(A + (size_t)s4.y * D + lane4);  \
    float4 v2 = *reinterpret_cast<const float4*>(A + (size_t)s4.z * D + lane4);  \
    float4 v3 = *reinterpret_cast<const float4*>(A + (size_t)s4.w * D + lane4);  \
    (acc).x += (v0.x + v1.x) + (v2.x + v3.x);                                    \
    (acc).y += (v0.y + v1.y) + (v2.y + v3.y);                                    \
    (acc).z += (v0.z + v1.z) + (v2.z + v3.z);                                    \
    (acc).w += (v0.w + v1.w) + (v2.w + v3.w);                                    \
} while (0)

__global__ void __launch_bounds__(256) aggregate_kernel(
    const float* __restrict__ A,
    const int*   __restrict__ csr,
    const int*   __restrict__ deg,
    const int*   __restrict__ in_deg,
    float*       __restrict__ msg)
{
    const int tx    = threadIdx.x & 31;
    const int wid   = threadIdx.x >> 5;
    const int lane4 = tx * 4;
    const int gr0 = blockIdx.x * 16 + wid * 2;
    const int gr1 = gr0 + 1;
    const bool ok0 = gr0 < N_NODES;
    const bool ok1 = gr1 < N_NODES;
    if (!ok0) return;

    int cnt0 = ok0 ? __ldg(deg + gr0) : 0;
    int cnt1 = ok1 ? __ldg(deg + gr1) : 0;
    if (cnt0 > CSR_STRIDE) cnt0 = CSR_STRIDE;
    if (cnt1 > CSR_STRIDE) cnt1 = CSR_STRIDE;
    const int* p0 = csr + (size_t)gr0 * CSR_STRIDE;
    const int* p1 = csr + (size_t)gr1 * CSR_STRIDE;

    float4 acc0 = make_float4(0.f, 0.f, 0.f, 0.f);
    float4 acc1 = make_float4(0.f, 0.f, 0.f, 0.f);

    const int nb0 = cnt0 >> 2;
    const int nb1 = cnt1 >> 2;
    const int nbm = max(nb0, nb1);
#pragma unroll 1
    for (int b = 0; b < nbm; ++b) {
        if (b < nb0) GATHER4(p0, b * 4, acc0);
        if (b < nb1) GATHER4(p1, b * 4, acc1);
    }
    for (int i = nb0 * 4; i < cnt0; ++i) {
        int s = __ldg(p0 + i);
        float4 v = *reinterpret_cast<const float4*>(A + (size_t)s * D + lane4);
        acc0.x += v.x; acc0.y += v.y; acc0.z += v.z; acc0.w += v.w;
    }
    for (int i = nb1 * 4; i < cnt1; ++i) {
        int s = __ldg(p1 + i);
        float4 v = *reinterpret_cast<const float4*>(A + (size_t)s * D + lane4);
        acc1.x += v.x; acc1.y += v.y; acc1.z += v.z; acc1.w += v.w;
    }

    {
        float inv = 1.0f / (float)max(__ldg(in_deg + gr0), 1);
        acc0.x *= inv; acc0.y *= inv; acc0.z *= inv; acc0.w *= inv;
        *reinterpret_cast<float4*>(msg + (size_t)gr0 * D + lane4) = acc0;
    }
    if (ok1) {
        float inv = 1.0f / (float)max(__ldg(in_deg + gr1), 1);
        acc1.x *= inv; acc1.y *= inv; acc1.z *= inv; acc1.w *= inv;
        *reinterpret_cast<float4*>(msg + (size_t)gr1 * D + lane4) = acc1;
    }
}

// ---------------------------------------------------------------------------
// STANDALONE GEMM: Out = A @ Wself + Msg @ Wneigh + bias (+LN+ReLU layer0).
// K=256 concat, f32x2 math, pipelined loads, dup-pair SMEM staging (R12
// phase-2 verbatim; smsg reads replaced by global Msg).
// Tile 64 rows x 128 cols, 256 threads, smem 17KB.
// ---------------------------------------------------------------------------
#define AS_STRIDE 36
#define GEMM_DYN_FLOATS (64 * AS_STRIDE + 2048)
#define GEMM_DYN_BYTES  (GEMM_DYN_FLOATS * 4)   // 17408

template <bool FUSE_LN>
__global__ void __launch_bounds__(256) sage_gemm_kernel(
    const float* __restrict__ A,       // [N,128] self input
    const float* __restrict__ Msg,     // [N,128] neighbor means
    const float* __restrict__ Wp_g,    // pre-permuted weights [16*2048]
    const float* __restrict__ bias,
    const float* __restrict__ ln_g,
    const float* __restrict__ ln_b,
    float*       __restrict__ Out)     // [N,128]
{
    __shared__ __align__(16) float As2[64 * AS_STRIDE];
    __shared__ __align__(16) float Wp[2048];

    const int t    = threadIdx.x;
    const int tx   = t & 31;
    const int ty   = t >> 5;
    const int row0 = blockIdx.x * 64;

    const int lr  = t >> 2;
    const int lk4 = (t & 3) << 2;
    const int grow_l = row0 + lr;
    const bool okl = grow_l < N_NODES;

    unsigned long long acc[8][2];
#pragma unroll
    for (int j = 0; j < 8; ++j) { acc[j][0] = 0ull; acc[j][1] = 0ull; }

    // initial loads (chunk 0)
    float4 a4 = okl ? *reinterpret_cast<const float4*>(A + (size_t)grow_l * 128 + lk4)
                    : make_float4(0.f, 0.f, 0.f, 0.f);
    float4 w0 = *reinterpret_cast<const float4*>(Wp_g + t * 4);
    float4 w1 = *reinterpret_cast<const float4*>(Wp_g + (t + 256) * 4);

#pragma unroll 1
    for (int kc = 0; kc < 16; ++kc) {
        __syncthreads();   // previous chunk's compute done -> As2/Wp free
        *reinterpret_cast<float4*>(As2 + lr * AS_STRIDE + lk4 * 2) =
            make_float4(a4.x, a4.x, a4.y, a4.y);
        *reinterpret_cast<float4*>(As2 + lr * AS_STRIDE + lk4 * 2 + 4) =
            make_float4(a4.z, a4.z, a4.w, a4.w);
        *reinterpret_cast<float4*>(Wp + t * 4)         = w0;
        *reinterpret_cast<float4*>(Wp + (t + 256) * 4) = w1;

        // issue next chunk's loads NOW; they land during the compute below
        if (kc < 15) {
            const int kn = kc + 1;
            const float* Asrc = (kn < 8) ? A : Msg;
            const int kb = (kn & 7) * 16;
            a4 = okl ? *reinterpret_cast<const float4*>(
                           Asrc + (size_t)grow_l * 128 + kb + lk4)
                     : make_float4(0.f, 0.f, 0.f, 0.f);
            w0 = *reinterpret_cast<const float4*>(Wp_g + kn * 2048 + t * 4);
            w1 = *reinterpret_cast<const float4*>(Wp_g + kn * 2048 + (t + 256) * 4);
        }
        __syncthreads();   // As2/Wp visible

#pragma unroll
        for (int m = 0; m < 8; ++m) {
            ulonglong2 wA = *reinterpret_cast<const ulonglong2*>(Wp + (2 * m) * 128 + tx * 4);
            ulonglong2 wB = *reinterpret_cast<const ulonglong2*>(Wp + (2 * m + 1) * 128 + tx * 4);
#pragma unroll
            for (int j = 0; j < 8; ++j) {
                ulonglong2 ap = *reinterpret_cast<const ulonglong2*>(
                    As2 + (ty + j * 8) * AS_STRIDE + m * 4);
                FMA_F32X2(acc[j][0], ap.x, wA.x);   // cols (tx, tx+32)
                FMA_F32X2(acc[j][1], ap.x, wA.y);   // cols (tx+64, tx+96)
                FMA_F32X2(acc[j][0], ap.y, wB.x);
                FMA_F32X2(acc[j][1], ap.y, wB.y);
            }
        }
    }

    // ================= Epilogue =================
    float bia[4], lg[4], lb[4];
#pragma unroll
    for (int c = 0; c < 4; ++c) {
        int col = tx + 32 * c;
        bia[c] = __ldg(bias + col);
        if (FUSE_LN) { lg[c] = __ldg(ln_g + col); lb[c] = __ldg(ln_b + col); }
    }

#pragma unroll
    for (int j = 0; j < 8; ++j) {
        int grow = row0 + ty + j * 8;
        float v[4];
        UNPACK_F32X2(v[0], v[1], acc[j][0]);
        UNPACK_F32X2(v[2], v[3], acc[j][1]);
#pragma unroll
        for (int c = 0; c < 4; ++c) v[c] += bia[c];

        if (FUSE_LN) {
            float s = v[0] + v[1] + v[2] + v[3];
#pragma unroll
            for (int o = 16; o > 0; o >>= 1) s += __shfl_xor_sync(0xffffffffu, s, o);
            float mu = s * (1.0f / 128.0f);
            float d2 = 0.f;
#pragma unroll
            for (int c = 0; c < 4; ++c) { float dd = v[c] - mu; d2 += dd * dd; }
#pragma unroll
            for (int o = 16; o > 0; o >>= 1) d2 += __shfl_xor_sync(0xffffffffu, d2, o);
            float rstd = rsqrtf(d2 * (1.0f / 128.0f) + 1e-5f);
#pragma unroll
            for (int c = 0; c < 4; ++c) {
                float y = (v[c] - mu) * rstd * lg[c] + lb[c];
                v[c] = fmaxf(y, 0.0f);
            }
        }

        if (grow < N_NODES) {
#pragma unroll
            for (int c = 0; c < 4; ++c)
                Out[(size_t)grow * 128 + tx + 32 * c] = v[c];
        }
    }
}

// ---------------------------------------------------------------------------
// Launch.  Inputs: feat, W_self0, W_neigh0, b0, W_self1, W_neigh1, b1,
//                  ln_g, ln_b, edge_src, edge_dst, in_deg
// Launch order: [memset, prep, fill, agg0, gemm0, agg1, gemm1]
// -> ncu 5th launch = gemm0.
// ---------------------------------------------------------------------------
extern "C" void kernel_launch(void* const* d_in, const int* in_sizes, int n_in,
                              void* d_out, int out_size)
{
    const float* feat = (const float*)d_in[0];
    const float* Ws0  = (const float*)d_in[1];
    const float* Wn0  = (const float*)d_in[2];
    const float* b0   = (const float*)d_in[3];
    const float* Ws1  = (const float*)d_in[4];
    const float* Wn1  = (const float*)d_in[5];
    const float* b1   = (const float*)d_in[6];
    const float* lng  = (const float*)d_in[7];
    const float* lnb  = (const float*)d_in[8];
    const int*   esrc = (const int*)d_in[9];
    const int*   edst = (const int*)d_in[10];
    const int*   indeg= (const int*)d_in[11];
    const int n_edges = in_sizes[9];

    float *h = nullptr, *msg = nullptr, *wperm = nullptr;
    int *cur = nullptr, *csr = nullptr;
    cudaGetSymbolAddress((void**)&h,     g_h);
    cudaGetSymbolAddress((void**)&msg,   g_msg);
    cudaGetSymbolAddress((void**)&cur,   g_cur);
    cudaGetSymbolAddress((void**)&csr,   g_csr);
    cudaGetSymbolAddress((void**)&wperm, g_wperm);

    const int eb          = (n_edges + 255) / 256;
    const int agg_blocks  = (N_NODES + 15) / 16;   // 6250 (16 nodes/CTA)
    const int gemm_blocks = (N_NODES + 63) / 64;   // 1563

    // (1) zero fill counters
    cudaMemsetAsync(cur, 0, N_NODES * sizeof(int), 0);
    // (2) weight permutation
    prep_w_kernel<<<(2 * 16 * 2048 + 255) / 256, 256>>>(Ws0, Wn0, Ws1, Wn1);
    // (3) fixed-stride CSR fill (cur becomes degree)
    fill_kernel<<<eb, 256>>>(esrc, edst, cur, csr, n_edges);

    // ---- Layer 0 ----
    aggregate_kernel<<<agg_blocks, 256>>>(feat, csr, cur, indeg, msg);
    sage_gemm_kernel<true><<<gemm_blocks, 256>>>(           // 5th: profiled
        feat, msg, wperm, b0, lng, lnb, h);

    // ---- Layer 1 ----
    aggregate_kernel<<<agg_blocks, 256>>>(h, csr, cur, indeg, msg);
    sage_gemm_kernel<false><<<gemm_blocks, 256>>>(
        h, msg, wperm + 16 * 2048, b1, lng, lnb, (float*)d_out);
}

// round 17
// speedup vs baseline: 1.9650x; 1.0787x over previous
#include <cuda_runtime.h>
#include <cstdint>

#define N_NODES 100000
#define D 128
#define CSR_STRIDE 64      // fixed slots per node (actual deg <= 64)

// ---------------------------------------------------------------------------
// Scratch (__device__ globals: allocation-free rule)
// ---------------------------------------------------------------------------
__device__ __align__(128) float g_h[(size_t)N_NODES * D];            // 51.2 MB
__device__ __align__(128) float g_msg[(size_t)N_NODES * D];          // 51.2 MB
__device__ __align__(128) int   g_cur[N_NODES];                      // fill counters -> degree
__device__ __align__(128) int   g_csr[(size_t)N_NODES * CSR_STRIDE]; // 25.6 MB
// Pre-permuted weights: [layer][kc 0..15][kk*128 + lane*4 + g] = W'[kc*16+kk][g*32+lane]
__device__ __align__(16) float g_wperm[2 * 16 * 2048];

#define FMA_F32X2(d, a, b) \
    asm("fma.rn.f32x2 %0, %1, %2, %0;" : "+l"(d) : "l"(a), "l"(b))
#define UNPACK_F32X2(lo, hi, in) \
    asm("mov.b64 {%0, %1}, %2;" : "=f"(lo), "=f"(hi) : "l"(in))
#define DUP_F32X2(d, a) \
    asm("mov.b64 %0, {%1, %1};" : "=l"(d) : "f"(a))

// ---------------------------------------------------------------------------
// Weight prep: permute both layers' [Wself;Wneigh] into GEMM SMEM layout
// ---------------------------------------------------------------------------
__global__ void prep_w_kernel(const float* __restrict__ Ws0, const float* __restrict__ Wn0,
                              const float* __restrict__ Ws1, const float* __restrict__ Wn1)
{
    int gid = blockIdx.x * blockDim.x + threadIdx.x;   // 65536
    if (gid >= 2 * 16 * 2048) return;
    int l  = gid >> 15;
    int r  = gid & 32767;
    int kc = r >> 11;
    int p  = r & 2047;
    int kk = p >> 7;
    int q  = p & 127;
    int lane = q >> 2;
    int g    = q & 3;
    int c = g * 32 + lane;
    int k = kc * 16 + kk;
    const float* Wsrc = (l == 0) ? ((k < 128) ? Ws0 : Wn0)
                                 : ((k < 128) ? Ws1 : Wn1);
    g_wperm[gid] = Wsrc[(size_t)(k & 127) * 128 + c];
}

// ---------------------------------------------------------------------------
// CSR fill (fixed stride). cur zeroed beforehand; becomes in-degree.
// ---------------------------------------------------------------------------
__global__ void fill_kernel(const int* __restrict__ src, const int* __restrict__ dst,
                            int* __restrict__ cur, int* __restrict__ csr, int n_edges)
{
    int i = blockIdx.x * blockDim.x + threadIdx.x;
    if (i < n_edges) {
        int d = dst[i];
        int pos = atomicAdd(cur + d, 1);
        if (pos < CSR_STRIDE)
            csr[(size_t)d * CSR_STRIDE + pos] = src[i];
    }
}

// ---------------------------------------------------------------------------
// STANDALONE aggregate: warp handles an interleaved PAIR of nodes (2 load
// chains). 16 nodes per 256-thread CTA, no barriers, pure gather. (frozen)
// ---------------------------------------------------------------------------
#define GATHER4(p, i, acc) do {                                                  \
    int4 s4 = *reinterpret_cast<const int4*>((p) + (i));                         \
    float4 v0 = *reinterpret_cast<const float4*>(A + (size_t)s4.x * D + lane4);  \
    float4 v1 = *reinterpret_cast<const float4*>(A + (size_t)s4.y * D + lane4);  \
    float4 v2 = *reinterpret_cast<const float4*>(A + (size_t)s4.z * D + lane4);  \
    float4 v3 = *reinterpret_cast<const float4*>(A + (size_t)s4.w * D + lane4);  \
    (acc).x += (v0.x + v1.x) + (v2.x + v3.x);                                    \
    (acc).y += (v0.y + v1.y) + (v2.y + v3.y);                                    \
    (acc).z += (v0.z + v1.z) + (v2.z + v3.z);                                    \
    (acc).w += (v0.w + v1.w) + (v2.w + v3.w);                                    \
} while (0)

__global__ void __launch_bounds__(256) aggregate_kernel(
    const float* __restrict__ A,
    const int*   __restrict__ csr,
    const int*   __restrict__ deg,
    const int*   __restrict__ in_deg,
    float*       __restrict__ msg)
{
    const int tx    = threadIdx.x & 31;
    const int wid   = threadIdx.x >> 5;
    const int lane4 = tx * 4;
    const int gr0 = blockIdx.x * 16 + wid * 2;
    const int gr1 = gr0 + 1;
    const bool ok0 = gr0 < N_NODES;
    const bool ok1 = gr1 < N_NODES;
    if (!ok0) return;

    int cnt0 = ok0 ? __ldg(deg + gr0) : 0;
    int cnt1 = ok1 ? __ldg(deg + gr1) : 0;
    if (cnt0 > CSR_STRIDE) cnt0 = CSR_STRIDE;
    if (cnt1 > CSR_STRIDE) cnt1 = CSR_STRIDE;
    const int* p0 = csr + (size_t)gr0 * CSR_STRIDE;
    const int* p1 = csr + (size_t)gr1 * CSR_STRIDE;

    float4 acc0 = make_float4(0.f, 0.f, 0.f, 0.f);
    float4 acc1 = make_float4(0.f, 0.f, 0.f, 0.f);

    const int nb0 = cnt0 >> 2;
    const int nb1 = cnt1 >> 2;
    const int nbm = max(nb0, nb1);
#pragma unroll 1
    for (int b = 0; b < nbm; ++b) {
        if (b < nb0) GATHER4(p0, b * 4, acc0);
        if (b < nb1) GATHER4(p1, b * 4, acc1);
    }
    for (int i = nb0 * 4; i < cnt0; ++i) {
        int s = __ldg(p0 + i);
        float4 v = *reinterpret_cast<const float4*>(A + (size_t)s * D + lane4);
        acc0.x += v.x; acc0.y += v.y; acc0.z += v.z; acc0.w += v.w;
    }
    for (int i = nb1 * 4; i < cnt1; ++i) {
        int s = __ldg(p1 + i);
        float4 v = *reinterpret_cast<const float4*>(A + (size_t)s * D + lane4);
        acc1.x += v.x; acc1.y += v.y; acc1.z += v.z; acc1.w += v.w;
    }

    {
        float inv = 1.0f / (float)max(__ldg(in_deg + gr0), 1);
        acc0.x *= inv; acc0.y *= inv; acc0.z *= inv; acc0.w *= inv;
        *reinterpret_cast<float4*>(msg + (size_t)gr0 * D + lane4) = acc0;
    }
    if (ok1) {
        float inv = 1.0f / (float)max(__ldg(in_deg + gr1), 1);
        acc1.x *= inv; acc1.y *= inv; acc1.z *= inv; acc1.w *= inv;
        *reinterpret_cast<float4*>(msg + (size_t)gr1 * D + lane4) = acc1;
    }
}

// ---------------------------------------------------------------------------
// STANDALONE GEMM: Out = A @ Wself + Msg @ Wneigh + bias (+LN+ReLU layer0).
// K=256 concat, f32x2 math, pipelined loads. A staged as SCALARS (1 STS.128,
// LDS.128 broadcast = 4 k's); (a,a) packs built in-register -> 25% fewer
// inner-loop L1 wavefronts than the dup-pair format.
// Tile 64 rows x 128 cols, 256 threads, smem 13KB.
// ---------------------------------------------------------------------------
#define AS_STRIDE 20       // 16 scalars + pad (20 mod 32 = 4 -> conflict-free)

template <bool FUSE_LN>
__global__ void __launch_bounds__(256) sage_gemm_kernel(
    const float* __restrict__ A,       // [N,128] self input
    const float* __restrict__ Msg,     // [N,128] neighbor means
    const float* __restrict__ Wp_g,    // pre-permuted weights [16*2048]
    const float* __restrict__ bias,
    const float* __restrict__ ln_g,
    const float* __restrict__ ln_b,
    float*       __restrict__ Out)     // [N,128]
{
    __shared__ __align__(16) float As2[64 * AS_STRIDE];
    __shared__ __align__(16) float Wp[2048];

    const int t    = threadIdx.x;
    const int tx   = t & 31;
    const int ty   = t >> 5;
    const int row0 = blockIdx.x * 64;

    const int lr  = t >> 2;
    const int lk4 = (t & 3) << 2;
    const int grow_l = row0 + lr;
    const bool okl = grow_l < N_NODES;

    unsigned long long acc[8][2];
#pragma unroll
    for (int j = 0; j < 8; ++j) { acc[j][0] = 0ull; acc[j][1] = 0ull; }

    // initial loads (chunk 0)
    float4 a4 = okl ? *reinterpret_cast<const float4*>(A + (size_t)grow_l * 128 + lk4)
                    : make_float4(0.f, 0.f, 0.f, 0.f);
    float4 w0 = *reinterpret_cast<const float4*>(Wp_g + t * 4);
    float4 w1 = *reinterpret_cast<const float4*>(Wp_g + (t + 256) * 4);

#pragma unroll 1
    for (int kc = 0; kc < 16; ++kc) {
        __syncthreads();   // previous chunk's compute done -> As2/Wp free
        *reinterpret_cast<float4*>(As2 + lr * AS_STRIDE + lk4) = a4;   // scalar A
        *reinterpret_cast<float4*>(Wp + t * 4)         = w0;
        *reinterpret_cast<float4*>(Wp + (t + 256) * 4) = w1;

        // issue next chunk's loads NOW; they land during the compute below
        if (kc < 15) {
            const int kn = kc + 1;
            const float* Asrc = (kn < 8) ? A : Msg;
            const int kb = (kn & 7) * 16;
            a4 = okl ? *reinterpret_cast<const float4*>(
                           Asrc + (size_t)grow_l * 128 + kb + lk4)
                     : make_float4(0.f, 0.f, 0.f, 0.f);
            w0 = *reinterpret_cast<const float4*>(Wp_g + kn * 2048 + t * 4);
            w1 = *reinterpret_cast<const float4*>(Wp_g + kn * 2048 + (t + 256) * 4);
        }
        __syncthreads();   // As2/Wp visible

        // 4 k's per m2 step: 4 W-LDS.128 + per-row 1 A-LDS.128 + reg dups
#pragma unroll
        for (int m2 = 0; m2 < 4; ++m2) {
            ulonglong2 wv0 = *reinterpret_cast<const ulonglong2*>(Wp + (4 * m2 + 0) * 128 + tx * 4);
            ulonglong2 wv1 = *reinterpret_cast<const ulonglong2*>(Wp + (4 * m2 + 1) * 128 + tx * 4);
            ulonglong2 wv2 = *reinterpret_cast<const ulonglong2*>(Wp + (4 * m2 + 2) * 128 + tx * 4);
            ulonglong2 wv3 = *reinterpret_cast<const ulonglong2*>(Wp + (4 * m2 + 3) * 128 + tx * 4);
#pragma unroll
            for (int j = 0; j < 8; ++j) {
                float4 av = *reinterpret_cast<const float4*>(
                    As2 + (ty + j * 8) * AS_STRIDE + m2 * 4);   // broadcast, 4 k's
                unsigned long long d0, d1, d2, d3;
                DUP_F32X2(d0, av.x);
                DUP_F32X2(d1, av.y);
                DUP_F32X2(d2, av.z);
                DUP_F32X2(d3, av.w);
                FMA_F32X2(acc[j][0], d0, wv0.x);
                FMA_F32X2(acc[j][1], d0, wv0.y);
                FMA_F32X2(acc[j][0], d1, wv1.x);
                FMA_F32X2(acc[j][1], d1, wv1.y);
                FMA_F32X2(acc[j][0], d2, wv2.x);
                FMA_F32X2(acc[j][1], d2, wv2.y);
                FMA_F32X2(acc[j][0], d3, wv3.x);
                FMA_F32X2(acc[j][1], d3, wv3.y);
            }
        }
    }

    // ================= Epilogue =================
    float bia[4], lg[4], lb[4];
#pragma unroll
    for (int c = 0; c < 4; ++c) {
        int col = tx + 32 * c;
        bia[c] = __ldg(bias + col);
        if (FUSE_LN) { lg[c] = __ldg(ln_g + col); lb[c] = __ldg(ln_b + col); }
    }

#pragma unroll
    for (int j = 0; j < 8; ++j) {
        int grow = row0 + ty + j * 8;
        float v[4];
        UNPACK_F32X2(v[0], v[1], acc[j][0]);
        UNPACK_F32X2(v[2], v[3], acc[j][1]);
#pragma unroll
        for (int c = 0; c < 4; ++c) v[c] += bia[c];

        if (FUSE_LN) {
            float s = v[0] + v[1] + v[2] + v[3];
#pragma unroll
            for (int o = 16; o > 0; o >>= 1) s += __shfl_xor_sync(0xffffffffu, s, o);
            float mu = s * (1.0f / 128.0f);
            float d2 = 0.f;
#pragma unroll
            for (int c = 0; c < 4; ++c) { float dd = v[c] - mu; d2 += dd * dd; }
#pragma unroll
            for (int o = 16; o > 0; o >>= 1) d2 += __shfl_xor_sync(0xffffffffu, d2, o);
            float rstd = rsqrtf(d2 * (1.0f / 128.0f) + 1e-5f);
#pragma unroll
            for (int c = 0; c < 4; ++c) {
                float y = (v[c] - mu) * rstd * lg[c] + lb[c];
                v[c] = fmaxf(y, 0.0f);
            }
        }

        if (grow < N_NODES) {
#pragma unroll
            for (int c = 0; c < 4; ++c)
                Out[(size_t)grow * 128 + tx + 32 * c] = v[c];
        }
    }
}

// ---------------------------------------------------------------------------
// Launch.  Inputs: feat, W_self0, W_neigh0, b0, W_self1, W_neigh1, b1,
//                  ln_g, ln_b, edge_src, edge_dst, in_deg
// Launch order: [memset, prep, fill, agg0, gemm0, agg1, gemm1]
// -> ncu 5th launch = gemm0.
// ---------------------------------------------------------------------------
extern "C" void kernel_launch(void* const* d_in, const int* in_sizes, int n_in,
                              void* d_out, int out_size)
{
    const float* feat = (const float*)d_in[0];
    const float* Ws0  = (const float*)d_in[1];
    const float* Wn0  = (const float*)d_in[2];
    const float* b0   = (const float*)d_in[3];
    const float* Ws1  = (const float*)d_in[4];
    const float* Wn1  = (const float*)d_in[5];
    const float* b1   = (const float*)d_in[6];
    const float* lng  = (const float*)d_in[7];
    const float* lnb  = (const float*)d_in[8];
    const int*   esrc = (const int*)d_in[9];
    const int*   edst = (const int*)d_in[10];
    const int*   indeg= (const int*)d_in[11];
    const int n_edges = in_sizes[9];

    float *h = nullptr, *msg = nullptr, *wperm = nullptr;
    int *cur = nullptr, *csr = nullptr;
    cudaGetSymbolAddress((void**)&h,     g_h);
    cudaGetSymbolAddress((void**)&msg,   g_msg);
    cudaGetSymbolAddress((void**)&cur,   g_cur);
    cudaGetSymbolAddress((void**)&csr,   g_csr);
    cudaGetSymbolAddress((void**)&wperm, g_wperm);

    const int eb          = (n_edges + 255) / 256;
    const int agg_blocks  = (N_NODES + 15) / 16;   // 6250 (16 nodes/CTA)
    const int gemm_blocks = (N_NODES + 63) / 64;   // 1563

    // (1) zero fill counters
    cudaMemsetAsync(cur, 0, N_NODES * sizeof(int), 0);
    // (2) weight permutation
    prep_w_kernel<<<(2 * 16 * 2048 + 255) / 256, 256>>>(Ws0, Wn0, Ws1, Wn1);
    // (3) fixed-stride CSR fill (cur becomes degree)
    fill_kernel<<<eb, 256>>>(esrc, edst, cur, csr, n_edges);

    // ---- Layer 0 ----
    aggregate_kernel<<<agg_blocks, 256>>>(feat, csr, cur, indeg, msg);
    sage_gemm_kernel<true><<<gemm_blocks, 256>>>(           // 5th: profiled
        feat, msg, wperm, b0, lng, lnb, h);

    // ---- Layer 1 ----
    aggregate_kernel<<<agg_blocks, 256>>>(h, csr, cur, indeg, msg);
    sage_gemm_kernel<false><<<gemm_blocks, 256>>>(
        h, msg, wperm + 16 * 2048, b1, lng, lnb, (float*)d_out);
}